// round 10
// baseline (speedup 1.0000x reference)
#include <cuda_runtime.h>
#include <math.h>
#include <limits.h>

#define HDIM 128
#define SDIM 32
#define KTOP 8
#define RPB  128                  // rows per block
#define NBLK 782                  // ceil(100000/128) — grid size, fixed by shapes
#define NCAND (NBLK * KTOP)       // 6256

// Scratch (__device__ globals; no allocation allowed)
__device__ float2 g_cand[NCAND];          // (value, index bits)
__device__ unsigned int g_ticket;         // monotonic across graph replays

__device__ __forceinline__ bool better(float va, int ia, float vb, int ib) {
    // jax.lax.top_k ordering: higher value first, ties -> lower index
    return (va > vb) || (va == vb && ia < ib);
}

__device__ __forceinline__ bool better2(float2 a, float2 b) {
    return (a.x > b.x) ||
           (a.x == b.x && __float_as_int(a.y) < __float_as_int(b.y));
}

__device__ __forceinline__ void insert_topk(float* lv, int* li, float v, int c) {
    if (better(v, c, lv[KTOP - 1], li[KTOP - 1])) {
        int j = KTOP - 1;
#pragma unroll
        for (; j > 0; --j) {
            if (better(v, c, lv[j - 1], li[j - 1])) {
                lv[j] = lv[j - 1];
                li[j] = li[j - 1];
            } else break;
        }
        lv[j] = v;
        li[j] = c;
    }
}

__device__ __forceinline__ void insert2(float2* ls, float2 v) {
    if (better2(v, ls[KTOP - 1])) {
        int j = KTOP - 1;
#pragma unroll
        for (; j > 0; --j) {
            if (better2(v, ls[j - 1])) ls[j] = ls[j - 1];
            else break;
        }
        ls[j] = v;
    }
}

// ---------------------------------------------------------------------------
// One kernel: sims (coalesced warp-per-row) + block top-8 + decoupled
// last-block finalize (merge + gather + scores).
// ---------------------------------------------------------------------------
__global__ void __launch_bounds__(256)
episodic_kernel(const float* __restrict__ q,
                const float* __restrict__ emb,
                const float* __restrict__ episodes,
                float* __restrict__ out,
                int C) {
    __shared__ float  sq[HDIM];
    __shared__ float  s_rqn;
    __shared__ float  s_sims[RPB];
    __shared__ float  sv[16 * KTOP];
    __shared__ int    si[16 * KTOP];
    __shared__ float2 sc[256 * KTOP];          // tail merge scratch (16 KB)
    __shared__ int    s_amlast;

    const int t    = threadIdx.x;
    const int lane = t & 31;
    const int w    = t >> 5;

    // ---- query row 0 + 1/||q|| ----
    if (t < HDIM) sq[t] = q[t];
    __syncthreads();
    if (t < 32) {
        const float4 a = reinterpret_cast<const float4*>(sq)[t];
        float s = a.x * a.x + a.y * a.y + a.z * a.z + a.w * a.w;
#pragma unroll
        for (int o = 16; o; o >>= 1) s += __shfl_xor_sync(0xffffffffu, s, o);
        if (t == 0) s_rqn = 1.0f / fmaxf(sqrtf(s), 1e-8f);
    }
    __syncthreads();
    const float rqn = s_rqn;
    const float4 q4 = reinterpret_cast<const float4*>(sq)[lane];

    // ---- sims: each warp streams 16 rows, 4 front-batched coalesced loads ----
    const float4* __restrict__ emb4 = reinterpret_cast<const float4*>(emb);
    const int base = blockIdx.x * RPB;
#pragma unroll
    for (int it = 0; it < 4; ++it) {
        const int loc0 = w * 16 + it * 4;
        float4 ev[4];
#pragma unroll
        for (int j = 0; j < 4; ++j) {
            const int r = min(base + loc0 + j, C - 1);
            ev[j] = emb4[(size_t)r * (HDIM / 4) + lane];
        }
        float dot[4], esq[4];
#pragma unroll
        for (int j = 0; j < 4; ++j) {
            dot[j] = ev[j].x * q4.x + ev[j].y * q4.y + ev[j].z * q4.z + ev[j].w * q4.w;
            esq[j] = ev[j].x * ev[j].x + ev[j].y * ev[j].y + ev[j].z * ev[j].z + ev[j].w * ev[j].w;
        }
#pragma unroll
        for (int o = 16; o; o >>= 1) {
#pragma unroll
            for (int j = 0; j < 4; ++j) {
                dot[j] += __shfl_xor_sync(0xffffffffu, dot[j], o);
                esq[j] += __shfl_xor_sync(0xffffffffu, esq[j], o);
            }
        }
        if (lane < 4) {
            const int r = base + loc0 + lane;
            s_sims[loc0 + lane] = (r < C)
                ? dot[lane] * rqn / fmaxf(sqrtf(esq[lane]), 1e-8f)
                : -INFINITY;
        }
    }
    __syncthreads();

    // ---- block top-8: 16 threads x 8 inserts, then 4-level merge ----
    if (t < 16) {
        float lv[KTOP]; int li[KTOP];
#pragma unroll
        for (int j = 0; j < KTOP; ++j) { lv[j] = -INFINITY; li[j] = INT_MAX; }
#pragma unroll
        for (int j = 0; j < 8; ++j)
            insert_topk(lv, li, s_sims[t * 8 + j], base + t * 8 + j);
#pragma unroll
        for (int j = 0; j < KTOP; ++j) { sv[t * KTOP + j] = lv[j]; si[t * KTOP + j] = li[j]; }
    }
    __syncthreads();
    for (int s = 8; s > 0; s >>= 1) {
        if (t < s) {
            float mv[KTOP]; int mi[KTOP];
            int a = 0, b = 0;
#pragma unroll
            for (int j = 0; j < KTOP; ++j) {
                const float va = sv[t * KTOP + a];       const int ia = si[t * KTOP + a];
                const float vb = sv[(t + s) * KTOP + b]; const int ib = si[(t + s) * KTOP + b];
                if (better(va, ia, vb, ib)) { mv[j] = va; mi[j] = ia; ++a; }
                else                        { mv[j] = vb; mi[j] = ib; ++b; }
            }
#pragma unroll
            for (int j = 0; j < KTOP; ++j) { sv[t * KTOP + j] = mv[j]; si[t * KTOP + j] = mi[j]; }
        }
        __syncthreads();
    }
    if (t < KTOP)
        g_cand[blockIdx.x * KTOP + t] = make_float2(sv[t], __int_as_float(si[t]));
    __syncthreads();

    // ---- release + ticket: ONE fence per block (thread 0 only) ----
    if (t == 0) {
        __threadfence();                                   // publish candidates
        const unsigned int old = atomicAdd(&g_ticket, 1u);
        s_amlast = ((old % gridDim.x) == gridDim.x - 1);
    }
    __syncthreads();
    if (!s_amlast) return;
    if (t == 0) __threadfence();                           // acquire (L1 inval)
    __syncthreads();

    // =======================================================================
    // Last block: merge NCAND candidates -> top-8, gather episodes, scores.
    // =======================================================================
    {
        // Per-thread top-8 over strided candidates; 4 waves of 8 front-batched
        // __ldcg loads (independent within a wave -> one latency round each).
        float2 ls[KTOP];
#pragma unroll
        for (int j = 0; j < KTOP; ++j)
            ls[j] = make_float2(-INFINITY, __int_as_float(INT_MAX));
#pragma unroll
        for (int wv = 0; wv < 4; ++wv) {
            float2 cd[8];
#pragma unroll
            for (int i = 0; i < 8; ++i) {
                const int c = (wv * 8 + i) * 256 + t;
                cd[i] = (c < NCAND) ? __ldcg(&g_cand[c])
                                    : make_float2(-INFINITY, __int_as_float(INT_MAX));
            }
#pragma unroll
            for (int i = 0; i < 8; ++i) insert2(ls, cd[i]);
        }
#pragma unroll
        for (int j = 0; j < KTOP; ++j) sc[t * KTOP + j] = ls[j];
    }
    __syncthreads();

    for (int s = 128; s > 0; s >>= 1) {
        if (t < s) {
            float2 m[KTOP];
            int a = 0, b = 0;
#pragma unroll
            for (int j = 0; j < KTOP; ++j) {
                const float2 va = sc[t * KTOP + a];
                const float2 vb = sc[(t + s) * KTOP + b];
                if (better2(va, vb)) { m[j] = va; ++a; }
                else                 { m[j] = vb; ++b; }
            }
#pragma unroll
            for (int j = 0; j < KTOP; ++j) sc[t * KTOP + j] = m[j];
        }
        __syncthreads();
    }
    // global top-8 in sc[0..7]

    // ---- gather 8 episodes [8,32,128]: 2 episodes per wave, 8 loads in flight
    int   idx[KTOP];
#pragma unroll
    for (int e = 0; e < KTOP; ++e) idx[e] = __float_as_int(sc[e].y);

    const float4* __restrict__ epi4 = reinterpret_cast<const float4*>(episodes);
    float4* __restrict__ out4 = reinterpret_cast<float4*>(out);
    const int EP4 = SDIM * HDIM / 4;          // 1024 float4 per episode
#pragma unroll
    for (int wv = 0; wv < 4; ++wv) {
        const int e0 = wv * 2, e1 = wv * 2 + 1;
        float4 v0[4], v1[4];
#pragma unroll
        for (int i = 0; i < 4; ++i) {
            const int off = t + i * 256;
            v0[i] = epi4[(size_t)idx[e0] * EP4 + off];
            v1[i] = epi4[(size_t)idx[e1] * EP4 + off];
        }
#pragma unroll
        for (int i = 0; i < 4; ++i) {
            const int off = t + i * 256;
            out4[e0 * EP4 + off] = v0[i];
            out4[e1 * EP4 + off] = v1[i];
        }
    }
    if (t < KTOP)
        out[KTOP * SDIM * HDIM + t] = sc[t].x;    // top_scores[0]
}

extern "C" void kernel_launch(void* const* d_in, const int* in_sizes, int n_in,
                              void* d_out, int out_size) {
    const float* query    = (const float*)d_in[0];  // [B, 128]
    const float* episodes = (const float*)d_in[1];  // [C, 32, 128]
    const float* emb      = (const float*)d_in[2];  // [C, 128]
    (void)n_in; (void)out_size;

    const int C = in_sizes[2] / HDIM;               // 100000
    const int nblk = (C + RPB - 1) / RPB;           // 782 == NBLK

    episodic_kernel<<<nblk, 256>>>(query, emb, episodes, (float*)d_out, C);
}

// round 11
// speedup vs baseline: 1.4389x; 1.4389x over previous
#include <cuda_runtime.h>
#include <math.h>
#include <limits.h>

#define HDIM 128
#define SDIM 32
#define KTOP 8
#define RPB  128                  // rows per block in K1
#define NBLK 782                  // ceil(100000/128)
#define NCAND (NBLK * KTOP)       // 6256
#define MT   512                  // merge threads in K2
#define CPT  13                   // ceil(NCAND/MT)

// Scratch (__device__ globals; no allocation allowed)
__device__ float2 g_cand[NCAND];  // (value, index bits)

__device__ __forceinline__ bool better(float va, int ia, float vb, int ib) {
    // jax.lax.top_k ordering: higher value first, ties -> lower index
    return (va > vb) || (va == vb && ia < ib);
}

__device__ __forceinline__ bool better2(float2 a, float2 b) {
    return (a.x > b.x) ||
           (a.x == b.x && __float_as_int(a.y) < __float_as_int(b.y));
}

__device__ __forceinline__ void insert_topk(float* lv, int* li, float v, int c) {
    if (better(v, c, lv[KTOP - 1], li[KTOP - 1])) {
        int j = KTOP - 1;
#pragma unroll
        for (; j > 0; --j) {
            if (better(v, c, lv[j - 1], li[j - 1])) {
                lv[j] = lv[j - 1];
                li[j] = li[j - 1];
            } else break;
        }
        lv[j] = v;
        li[j] = c;
    }
}

__device__ __forceinline__ void insert2(float2* ls, float2 v) {
    if (better2(v, ls[KTOP - 1])) {
        int j = KTOP - 1;
#pragma unroll
        for (; j > 0; --j) {
            if (better2(v, ls[j - 1])) ls[j] = ls[j - 1];
            else break;
        }
        ls[j] = v;
    }
}

// ---------------------------------------------------------------------------
// K1: cosine sims (coalesced warp-per-row, 16 rows/warp) + block top-8.
// Fence-free producer; kernel boundary orders the candidate stores.
// ---------------------------------------------------------------------------
__global__ void __launch_bounds__(256)
sims_topk(const float* __restrict__ q,
          const float* __restrict__ emb,
          int C) {
    __shared__ float sq[HDIM];
    __shared__ float s_rqn;
    __shared__ float s_sims[RPB];
    __shared__ float sv[16 * KTOP];
    __shared__ int   si[16 * KTOP];

    const int t    = threadIdx.x;
    const int lane = t & 31;
    const int w    = t >> 5;

    if (t < HDIM) sq[t] = q[t];               // query row 0
    __syncthreads();
    if (t < 32) {
        const float4 a = reinterpret_cast<const float4*>(sq)[t];
        float s = a.x * a.x + a.y * a.y + a.z * a.z + a.w * a.w;
#pragma unroll
        for (int o = 16; o; o >>= 1) s += __shfl_xor_sync(0xffffffffu, s, o);
        if (t == 0) s_rqn = 1.0f / fmaxf(sqrtf(s), 1e-8f);
    }
    __syncthreads();
    const float rqn = s_rqn;
    const float4 q4 = reinterpret_cast<const float4*>(sq)[lane];

    const float4* __restrict__ emb4 = reinterpret_cast<const float4*>(emb);
    const int base = blockIdx.x * RPB;

#pragma unroll
    for (int it = 0; it < 4; ++it) {
        const int loc0 = w * 16 + it * 4;
        float4 ev[4];
#pragma unroll
        for (int j = 0; j < 4; ++j) {
            const int r = min(base + loc0 + j, C - 1);
            ev[j] = emb4[(size_t)r * (HDIM / 4) + lane];
        }
        float dot[4], esq[4];
#pragma unroll
        for (int j = 0; j < 4; ++j) {
            dot[j] = ev[j].x * q4.x + ev[j].y * q4.y + ev[j].z * q4.z + ev[j].w * q4.w;
            esq[j] = ev[j].x * ev[j].x + ev[j].y * ev[j].y + ev[j].z * ev[j].z + ev[j].w * ev[j].w;
        }
#pragma unroll
        for (int o = 16; o; o >>= 1) {
#pragma unroll
            for (int j = 0; j < 4; ++j) {
                dot[j] += __shfl_xor_sync(0xffffffffu, dot[j], o);
                esq[j] += __shfl_xor_sync(0xffffffffu, esq[j], o);
            }
        }
        if (lane < 4) {
            const int r = base + loc0 + lane;
            s_sims[loc0 + lane] = (r < C)
                ? dot[lane] * rqn / fmaxf(sqrtf(esq[lane]), 1e-8f)
                : -INFINITY;
        }
    }
    __syncthreads();

    // Block top-8 of 128 sims: 16 threads x 8 inserts, then 4-level merge.
    if (t < 16) {
        float lv[KTOP]; int li[KTOP];
#pragma unroll
        for (int j = 0; j < KTOP; ++j) { lv[j] = -INFINITY; li[j] = INT_MAX; }
#pragma unroll
        for (int j = 0; j < 8; ++j)
            insert_topk(lv, li, s_sims[t * 8 + j], base + t * 8 + j);
#pragma unroll
        for (int j = 0; j < KTOP; ++j) { sv[t * KTOP + j] = lv[j]; si[t * KTOP + j] = li[j]; }
    }
    __syncthreads();
    for (int s = 8; s > 0; s >>= 1) {
        if (t < s) {
            float mv[KTOP]; int mi[KTOP];
            int a = 0, b = 0;
#pragma unroll
            for (int j = 0; j < KTOP; ++j) {
                const float va = sv[t * KTOP + a];       const int ia = si[t * KTOP + a];
                const float vb = sv[(t + s) * KTOP + b]; const int ib = si[(t + s) * KTOP + b];
                if (better(va, ia, vb, ib)) { mv[j] = va; mi[j] = ia; ++a; }
                else                        { mv[j] = vb; mi[j] = ib; ++b; }
            }
#pragma unroll
            for (int j = 0; j < KTOP; ++j) { sv[t * KTOP + j] = mv[j]; si[t * KTOP + j] = mi[j]; }
        }
        __syncthreads();
    }
    if (t < KTOP)
        g_cand[blockIdx.x * KTOP + t] = make_float2(sv[t], __int_as_float(si[t]));
}

// ---------------------------------------------------------------------------
// K2: block 0 merges 6256 candidates -> top-8, gathers episodes, writes scores.
// Launched with grid=148 to escape the low-grid SM issue throttle; blocks
// 1..147 exit immediately.
// ---------------------------------------------------------------------------
__global__ void __launch_bounds__(1024)
final_gather(const float* __restrict__ episodes,
             float* __restrict__ out) {
    if (blockIdx.x != 0) return;

    __shared__ float2 sc[MT * KTOP];          // 32 KB
    const int t = threadIdx.x;

    if (t < MT) {
        // Front-batched candidate loads: CPT independent predicated LDG.64.
        float2 cd[CPT];
#pragma unroll
        for (int r = 0; r < CPT; ++r) {
            const int c = t + r * MT;
            cd[r] = (c < NCAND) ? g_cand[c]
                                : make_float2(-INFINITY, __int_as_float(INT_MAX));
        }
        float2 ls[KTOP];
#pragma unroll
        for (int j = 0; j < KTOP; ++j)
            ls[j] = make_float2(-INFINITY, __int_as_float(INT_MAX));
#pragma unroll
        for (int r = 0; r < CPT; ++r) insert2(ls, cd[r]);
#pragma unroll
        for (int j = 0; j < KTOP; ++j) sc[t * KTOP + j] = ls[j];
    }
    __syncthreads();

    // 9-level merge tree: 512 sorted lists -> 1.
    for (int s = MT / 2; s > 0; s >>= 1) {
        if (t < s) {
            float2 m[KTOP];
            int a = 0, b = 0;
#pragma unroll
            for (int j = 0; j < KTOP; ++j) {
                const float2 va = sc[t * KTOP + a];
                const float2 vb = sc[(t + s) * KTOP + b];
                if (better2(va, vb)) { m[j] = va; ++a; }
                else                 { m[j] = vb; ++b; }
            }
#pragma unroll
            for (int j = 0; j < KTOP; ++j) sc[t * KTOP + j] = m[j];
        }
        __syncthreads();
    }
    // global top-8 in sc[0..7]

    // Gather: thread t handles float4 column t of each of the 8 episodes.
    const float4* __restrict__ epi4 = reinterpret_cast<const float4*>(episodes);
    float4* __restrict__ out4 = reinterpret_cast<float4*>(out);
    float4 vals[KTOP];
#pragma unroll
    for (int e = 0; e < KTOP; ++e) {
        const int idx = __float_as_int(sc[e].y);
        vals[e] = epi4[(size_t)idx * (SDIM * HDIM / 4) + t];
    }
#pragma unroll
    for (int e = 0; e < KTOP; ++e)
        out4[e * (SDIM * HDIM / 4) + t] = vals[e];

    if (t < KTOP)
        out[KTOP * SDIM * HDIM + t] = sc[t].x;   // top_scores[0]
}

extern "C" void kernel_launch(void* const* d_in, const int* in_sizes, int n_in,
                              void* d_out, int out_size) {
    const float* query    = (const float*)d_in[0];  // [B, 128]
    const float* episodes = (const float*)d_in[1];  // [C, 32, 128]
    const float* emb      = (const float*)d_in[2];  // [C, 128]
    (void)n_in; (void)out_size;

    const int C = in_sizes[2] / HDIM;               // 100000
    const int nblk = (C + RPB - 1) / RPB;           // 782 == NBLK

    sims_topk<<<nblk, 256>>>(query, emb, C);
    final_gather<<<148, 1024>>>(episodes, (float*)d_out);
}